// round 1
// baseline (speedup 1.0000x reference)
#include <cuda_runtime.h>
#include <cstdint>

#define BB 2
#define NN 2048
#define CC 256
#define HH 8
#define HD 32
#define DA 36            // augmented head dim: 32 + 3 (points) + 1 (const)
#define M_TOT (BB*NN)    // 4096
#define QK_SCALE 0.17677669529663687f   // 1/sqrt(32)

// ---------------- scratch (static device memory, no allocation) --------------
__device__ float g_q[(size_t)BB*HH*NN*DA];    // [b][h][n][36]  augmented queries
__device__ float g_k[(size_t)BB*HH*NN*DA];    // [b][h][n][36]  augmented keys
__device__ float g_v[(size_t)BB*HH*NN*HD];    // [b][h][n][32]
__device__ float g_att[(size_t)M_TOT*CC];     // attention output [b*n][256]
__device__ float g_o[(size_t)M_TOT*CC];       // out-proj (+bias) [b*n][256]

// =============================================================================
// SGEMM mainloop: 128x128 tile, BK=8, 8x8 per thread, 256 threads.
// Computes acc[8][8] = A[r0:+128, :256] @ W[:256, c0:+128]
// =============================================================================
__device__ __forceinline__ void gemm_mainloop(const float* __restrict__ A,
                                              const float* __restrict__ W,
                                              int r0, int c0,
                                              float acc[8][8]) {
    __shared__ __align__(16) float As[8][132];   // padded (transposed A tile)
    __shared__ __align__(16) float Bs[8][128];

    const int tid = threadIdx.x;
    const int tx = tid & 15;
    const int ty = tid >> 4;

    const int arow = tid >> 1;          // 0..127
    const int acg  = tid & 1;           // 0..1
    const int brow = tid >> 5;          // 0..7
    const int bcg  = tid & 31;          // 0..31

    for (int kk = 0; kk < CC; kk += 8) {
        // load A tile (transposed into As[k][row])
        float4 av = *(const float4*)(A + (size_t)(r0 + arow) * CC + kk + acg * 4);
        As[acg*4 + 0][arow] = av.x;
        As[acg*4 + 1][arow] = av.y;
        As[acg*4 + 2][arow] = av.z;
        As[acg*4 + 3][arow] = av.w;
        // load W tile
        *(float4*)&Bs[brow][bcg*4] =
            *(const float4*)(W + (size_t)(kk + brow) * CC + c0 + bcg * 4);
        __syncthreads();

        #pragma unroll
        for (int k = 0; k < 8; k++) {
            float4 a0 = *(const float4*)&As[k][ty*8];
            float4 a1 = *(const float4*)&As[k][ty*8 + 4];
            float4 b0 = *(const float4*)&Bs[k][tx*8];
            float4 b1 = *(const float4*)&Bs[k][tx*8 + 4];
            float a[8] = {a0.x,a0.y,a0.z,a0.w,a1.x,a1.y,a1.z,a1.w};
            float b[8] = {b0.x,b0.y,b0.z,b0.w,b1.x,b1.y,b1.z,b1.w};
            #pragma unroll
            for (int i = 0; i < 8; i++)
                #pragma unroll
                for (int j = 0; j < 8; j++)
                    acc[i][j] += a[i] * b[j];
        }
        __syncthreads();
    }
}

// =============================================================================
// QKV projection GEMM. blockIdx.z selects Q/K/V. Writes directly into the
// augmented per-head layouts.
// =============================================================================
__global__ void __launch_bounds__(256)
gemm_qkv(const float* __restrict__ feat,
         const float* __restrict__ Wq, const float* __restrict__ Wk,
         const float* __restrict__ Wv,
         const float* __restrict__ bq, const float* __restrict__ bk,
         const float* __restrict__ bv) {
    const int z  = blockIdx.z;
    const int r0 = blockIdx.x * 128;
    const int c0 = blockIdx.y * 128;
    const float* W    = (z == 0) ? Wq : (z == 1) ? Wk : Wv;
    const float* bias = (z == 0) ? bq : (z == 1) ? bk : bv;

    float acc[8][8];
    #pragma unroll
    for (int i = 0; i < 8; i++)
        #pragma unroll
        for (int j = 0; j < 8; j++) acc[i][j] = 0.f;

    gemm_mainloop(feat, W, r0, c0, acc);

    const int tx = threadIdx.x & 15;
    const int ty = threadIdx.x >> 4;
    #pragma unroll
    for (int i = 0; i < 8; i++) {
        int m = r0 + ty*8 + i;
        int b = m >> 11;
        int n = m & (NN - 1);
        #pragma unroll
        for (int j = 0; j < 8; j++) {
            int c = c0 + tx*8 + j;
            int h = c >> 5;
            int d = c & 31;
            float val = acc[i][j] + bias[c];
            size_t idx = (((size_t)b*HH + h)*NN + n);
            if (z == 0)       g_q[idx*DA + d] = val * QK_SCALE;
            else if (z == 1)  g_k[idx*DA + d] = val;
            else              g_v[idx*HD + d] = val;
        }
    }
}

// =============================================================================
// Output projection GEMM: g_att @ Wo + bo -> g_o
// =============================================================================
__global__ void __launch_bounds__(256)
gemm_o(const float* __restrict__ Wo, const float* __restrict__ bo) {
    const int r0 = blockIdx.x * 128;
    const int c0 = blockIdx.y * 128;

    float acc[8][8];
    #pragma unroll
    for (int i = 0; i < 8; i++)
        #pragma unroll
        for (int j = 0; j < 8; j++) acc[i][j] = 0.f;

    gemm_mainloop(g_att, Wo, r0, c0, acc);

    const int tx = threadIdx.x & 15;
    const int ty = threadIdx.x >> 4;
    #pragma unroll
    for (int i = 0; i < 8; i++) {
        int m = r0 + ty*8 + i;
        #pragma unroll
        for (int j = 0; j < 8; j++) {
            int c = c0 + tx*8 + j;
            g_o[(size_t)m*CC + c] = acc[i][j] + bo[c];
        }
    }
}

// =============================================================================
// Fill augmented dims of q~ and k~ from points.
// q~[32..34] = 2*p, q~[35] = 1 ; k~[32..34] = p, k~[35] = -|p|^2
// =============================================================================
__global__ void pack_points(const float* __restrict__ pts) {
    int m = blockIdx.x * blockDim.x + threadIdx.x;
    if (m >= M_TOT) return;
    int b = m >> 11;
    int n = m & (NN - 1);
    float px = pts[m*3 + 0];
    float py = pts[m*3 + 1];
    float pz = pts[m*3 + 2];
    float p2 = px*px + py*py + pz*pz;
    #pragma unroll
    for (int h = 0; h < HH; h++) {
        size_t base = (((size_t)b*HH + h)*NN + n) * DA;
        g_q[base + 32] = 2.f*px;
        g_q[base + 33] = 2.f*py;
        g_q[base + 34] = 2.f*pz;
        g_q[base + 35] = 1.f;
        g_k[base + 32] = px;
        g_k[base + 33] = py;
        g_k[base + 34] = pz;
        g_k[base + 35] = -p2;
    }
}

// =============================================================================
// Attention: one thread per (b,h,query). Streams 32-key tiles through smem.
// Logits bounded above (<= qk_max + |p_n|^2) so no max-tracking is needed.
// =============================================================================
__global__ void __launch_bounds__(256)
attn_kernel() {
    const int tid  = threadIdx.x;
    const int bh   = blockIdx.y;                 // 0..15
    const int qrow = blockIdx.x * 256 + tid;

    // load augmented query (36 floats = 9 float4)
    const float4* qp = (const float4*)(g_q + ((size_t)bh*NN + qrow) * DA);
    float q[DA];
    #pragma unroll
    for (int t = 0; t < 9; t++) {
        float4 v4 = qp[t];
        q[4*t+0] = v4.x; q[4*t+1] = v4.y; q[4*t+2] = v4.z; q[4*t+3] = v4.w;
    }

    float acc[HD];
    #pragma unroll
    for (int d = 0; d < HD; d++) acc[d] = 0.f;
    float l = 0.f;

    __shared__ __align__(16) float sk[32 * DA];   // 4608 B
    __shared__ __align__(16) float sv[32 * HD];   // 4096 B

    const float4* kb = (const float4*)(g_k + (size_t)bh * NN * DA);
    const float4* vb = (const float4*)(g_v + (size_t)bh * NN * HD);

    for (int kt = 0; kt < NN/32; kt++) {
        __syncthreads();
        // copy 32x36 keys (288 float4) + 32x32 values (256 float4)
        float4* skv = (float4*)sk;
        const float4* ksrc = kb + kt * 288;
        skv[tid] = ksrc[tid];
        if (tid < 32) skv[256 + tid] = ksrc[256 + tid];
        ((float4*)sv)[tid] = vb[kt * 256 + tid];
        __syncthreads();

        #pragma unroll 2
        for (int kk = 0; kk < 32; kk++) {
            const float* kp = sk + kk * DA;
            float d0 = 0.f, d1 = 0.f, d2 = 0.f, d3 = 0.f;
            #pragma unroll
            for (int t = 0; t < 9; t++) {
                float4 kv = *(const float4*)(kp + 4*t);
                d0 += q[4*t+0] * kv.x;
                d1 += q[4*t+1] * kv.y;
                d2 += q[4*t+2] * kv.z;
                d3 += q[4*t+3] * kv.w;
            }
            float p = __expf((d0 + d1) + (d2 + d3));
            l += p;
            const float* vp = sv + kk * HD;
            #pragma unroll
            for (int t = 0; t < 8; t++) {
                float4 vv = *(const float4*)(vp + 4*t);
                acc[4*t+0] += p * vv.x;
                acc[4*t+1] += p * vv.y;
                acc[4*t+2] += p * vv.z;
                acc[4*t+3] += p * vv.w;
            }
        }
    }

    float inv = 1.f / l;
    int b = bh >> 3;
    int h = bh & 7;
    float* op = g_att + ((size_t)(b*NN + qrow)) * CC + h * HD;
    #pragma unroll
    for (int t = 0; t < 8; t++) {
        float4 o4 = make_float4(acc[4*t+0]*inv, acc[4*t+1]*inv,
                                acc[4*t+2]*inv, acc[4*t+3]*inv);
        *(float4*)(op + 4*t) = o4;
    }
}

// =============================================================================
// Residual + LayerNorm: out = LN(feature + g_o) * g + b
// =============================================================================
__global__ void __launch_bounds__(256)
ln_kernel(const float* __restrict__ feat,
          const float* __restrict__ ln_g, const float* __restrict__ ln_b,
          float* __restrict__ out) {
    const int m = blockIdx.x;
    const int c = threadIdx.x;
    float f = feat[(size_t)m*CC + c] + g_o[(size_t)m*CC + c];

    __shared__ float red[256];
    red[c] = f;
    __syncthreads();
    #pragma unroll
    for (int s = 128; s > 0; s >>= 1) {
        if (c < s) red[c] += red[c + s];
        __syncthreads();
    }
    float mu = red[0] * (1.f/256.f);
    __syncthreads();

    float d = f - mu;
    red[c] = d * d;
    __syncthreads();
    #pragma unroll
    for (int s = 128; s > 0; s >>= 1) {
        if (c < s) red[c] += red[c + s];
        __syncthreads();
    }
    float var = red[0] * (1.f/256.f);

    out[(size_t)m*CC + c] = d * rsqrtf(var + 1e-5f) * ln_g[c] + ln_b[c];
}

// =============================================================================
extern "C" void kernel_launch(void* const* d_in, const int* in_sizes, int n_in,
                              void* d_out, int out_size) {
    const float* feature = (const float*)d_in[0];
    const float* points  = (const float*)d_in[1];
    const float* Wq = (const float*)d_in[2];
    const float* bq = (const float*)d_in[3];
    const float* Wk = (const float*)d_in[4];
    const float* bk = (const float*)d_in[5];
    const float* Wv = (const float*)d_in[6];
    const float* bv = (const float*)d_in[7];
    const float* Wo = (const float*)d_in[8];
    const float* bo = (const float*)d_in[9];
    const float* ln_g = (const float*)d_in[10];
    const float* ln_b = (const float*)d_in[11];
    float* out = (float*)d_out;

    dim3 gq(M_TOT/128, CC/128, 3);          // 32 x 2 x 3
    gemm_qkv<<<gq, 256>>>(feature, Wq, Wk, Wv, bq, bk, bv);

    pack_points<<<(M_TOT + 255)/256, 256>>>(points);

    dim3 ga(NN/256, BB*HH);                 // 8 x 16
    attn_kernel<<<ga, 256>>>();

    dim3 go(M_TOT/128, CC/128);             // 32 x 2
    gemm_o<<<go, 256>>>(Wo, bo);

    ln_kernel<<<M_TOT, 256>>>(feature, ln_g, ln_b, out);
}

// round 2
// speedup vs baseline: 1.0991x; 1.0991x over previous
#include <cuda_runtime.h>
#include <cstdint>

#define BB 2
#define NN 2048
#define CC 256
#define HH 8
#define HD 32
#define DA 36            // augmented head dim: 32 + 3 (points) + 1 (const)
#define M_TOT (BB*NN)    // 4096
#define QK_SCALE 0.17677669529663687f   // 1/sqrt(32)

// ---------------- scratch (static device memory, no allocation) --------------
__device__ float g_q[(size_t)BB*HH*NN*DA];    // [b][h][n][36]  augmented queries
__device__ float g_k[(size_t)BB*HH*NN*DA];    // [b][h][n][36]  augmented keys
__device__ float g_v[(size_t)BB*HH*NN*HD];    // [b][h][n][32]
__device__ float g_att[(size_t)M_TOT*CC];     // attention output [b*n][256]
__device__ float g_o[(size_t)M_TOT*CC];       // out-proj (+bias) [b*n][256]

// ---------------- packed f32x2 helpers (Blackwell 2x fp32 pipe) --------------
typedef unsigned long long u64;

__device__ __forceinline__ u64 ffma2(u64 a, u64 b, u64 c) {
    u64 d;
    asm("fma.rn.f32x2 %0, %1, %2, %3;" : "=l"(d) : "l"(a), "l"(b), "l"(c));
    return d;
}
__device__ __forceinline__ u64 fmul2(u64 a, u64 b) {
    u64 d;
    asm("mul.rn.f32x2 %0, %1, %2;" : "=l"(d) : "l"(a), "l"(b));
    return d;
}
__device__ __forceinline__ u64 pack2(float lo, float hi) {
    u64 r;
    asm("mov.b64 %0, {%1, %2};" : "=l"(r) : "f"(lo), "f"(hi));
    return r;
}
__device__ __forceinline__ float2 unpack2(u64 v) {
    float lo, hi;
    asm("mov.b64 {%0, %1}, %2;" : "=f"(lo), "=f"(hi) : "l"(v));
    return make_float2(lo, hi);
}

// =============================================================================
// SGEMM mainloop: 64x64 tile, BK=16, 4x4 per thread (paired rows), 256 threads.
// acc2[pair][col]: pair 0 = rows {ty*4+0, ty*4+1}, pair 1 = rows {ty*4+2, +3}
// =============================================================================
__device__ __forceinline__ void gemm64_mainloop(const float* __restrict__ A,
                                                const float* __restrict__ W,
                                                int r0, int c0,
                                                u64 acc2[2][4]) {
    __shared__ __align__(16) float As[16][68];   // transposed A tile, padded
    __shared__ __align__(16) float Bs[16][64];

    const int tid = threadIdx.x;
    const int tx = tid & 15;
    const int ty = tid >> 4;
    const int arow = tid >> 2;          // 0..63
    const int acg  = tid & 3;           // 0..3  (k-group of 4)
    const int brow = tid >> 4;          // 0..15
    const int bcol = (tid & 15) * 4;

    for (int kk = 0; kk < CC; kk += 16) {
        float4 av = *(const float4*)(A + (size_t)(r0 + arow) * CC + kk + acg * 4);
        As[acg*4 + 0][arow] = av.x;
        As[acg*4 + 1][arow] = av.y;
        As[acg*4 + 2][arow] = av.z;
        As[acg*4 + 3][arow] = av.w;
        *(float4*)&Bs[brow][bcol] =
            *(const float4*)(W + (size_t)(kk + brow) * CC + c0 + bcol);
        __syncthreads();

        #pragma unroll
        for (int k = 0; k < 16; k++) {
            ulonglong2 a2 = *(const ulonglong2*)&As[k][ty*4];
            float4 b4 = *(const float4*)&Bs[k][tx*4];
            u64 b0 = pack2(b4.x, b4.x);
            u64 b1 = pack2(b4.y, b4.y);
            u64 b2 = pack2(b4.z, b4.z);
            u64 b3 = pack2(b4.w, b4.w);
            acc2[0][0] = ffma2(a2.x, b0, acc2[0][0]);
            acc2[0][1] = ffma2(a2.x, b1, acc2[0][1]);
            acc2[0][2] = ffma2(a2.x, b2, acc2[0][2]);
            acc2[0][3] = ffma2(a2.x, b3, acc2[0][3]);
            acc2[1][0] = ffma2(a2.y, b0, acc2[1][0]);
            acc2[1][1] = ffma2(a2.y, b1, acc2[1][1]);
            acc2[1][2] = ffma2(a2.y, b2, acc2[1][2]);
            acc2[1][3] = ffma2(a2.y, b3, acc2[1][3]);
        }
        __syncthreads();
    }
}

// =============================================================================
// QKV projection GEMM. blockIdx.z selects Q/K/V. Scatters into augmented
// per-head layouts.
// =============================================================================
__global__ void __launch_bounds__(256)
gemm_qkv(const float* __restrict__ feat,
         const float* __restrict__ Wq, const float* __restrict__ Wk,
         const float* __restrict__ Wv,
         const float* __restrict__ bq, const float* __restrict__ bk,
         const float* __restrict__ bv) {
    const int z  = blockIdx.z;
    const int r0 = blockIdx.x * 64;
    const int c0 = blockIdx.y * 64;
    const float* W    = (z == 0) ? Wq : (z == 1) ? Wk : Wv;
    const float* bias = (z == 0) ? bq : (z == 1) ? bk : bv;

    u64 acc2[2][4];
    #pragma unroll
    for (int i = 0; i < 2; i++)
        #pragma unroll
        for (int j = 0; j < 4; j++) acc2[i][j] = 0ull;

    gemm64_mainloop(feat, W, r0, c0, acc2);

    const int tx = threadIdx.x & 15;
    const int ty = threadIdx.x >> 4;
    #pragma unroll
    for (int ip = 0; ip < 2; ip++) {
        #pragma unroll
        for (int j = 0; j < 4; j++) {
            float2 f = unpack2(acc2[ip][j]);
            int c = c0 + tx*4 + j;
            int h = c >> 5;
            int d = c & 31;
            float bcol = bias[c];
            #pragma unroll
            for (int half = 0; half < 2; half++) {
                int m = r0 + ty*4 + ip*2 + half;
                int b = m >> 11;
                int n = m & (NN - 1);
                float val = (half ? f.y : f.x) + bcol;
                size_t idx = (((size_t)b*HH + h)*NN + n);
                if (z == 0)       g_q[idx*DA + d] = val * QK_SCALE;
                else if (z == 1)  g_k[idx*DA + d] = val;
                else              g_v[idx*HD + d] = val;
            }
        }
    }
}

// =============================================================================
// Output projection GEMM: g_att @ Wo + bo -> g_o
// =============================================================================
__global__ void __launch_bounds__(256)
gemm_o(const float* __restrict__ Wo, const float* __restrict__ bo) {
    const int r0 = blockIdx.x * 64;
    const int c0 = blockIdx.y * 64;

    u64 acc2[2][4];
    #pragma unroll
    for (int i = 0; i < 2; i++)
        #pragma unroll
        for (int j = 0; j < 4; j++) acc2[i][j] = 0ull;

    gemm64_mainloop(g_att, Wo, r0, c0, acc2);

    const int tx = threadIdx.x & 15;
    const int ty = threadIdx.x >> 4;
    #pragma unroll
    for (int ip = 0; ip < 2; ip++) {
        #pragma unroll
        for (int j = 0; j < 4; j++) {
            float2 f = unpack2(acc2[ip][j]);
            int c = c0 + tx*4 + j;
            float bc = bo[c];
            int m0 = r0 + ty*4 + ip*2;
            g_o[(size_t)m0*CC + c]       = f.x + bc;
            g_o[(size_t)(m0+1)*CC + c]   = f.y + bc;
        }
    }
}

// =============================================================================
// Fill augmented dims of q~ and k~ from points.
// q~[32..34] = 2*p, q~[35] = 1 ; k~[32..34] = p, k~[35] = -|p|^2
// =============================================================================
__global__ void pack_points(const float* __restrict__ pts) {
    int m = blockIdx.x * blockDim.x + threadIdx.x;
    if (m >= M_TOT) return;
    int b = m >> 11;
    int n = m & (NN - 1);
    float px = pts[m*3 + 0];
    float py = pts[m*3 + 1];
    float pz = pts[m*3 + 2];
    float p2 = px*px + py*py + pz*pz;
    #pragma unroll
    for (int h = 0; h < HH; h++) {
        size_t base = (((size_t)b*HH + h)*NN + n) * DA;
        g_q[base + 32] = 2.f*px;
        g_q[base + 33] = 2.f*py;
        g_q[base + 34] = 2.f*pz;
        g_q[base + 35] = 1.f;
        g_k[base + 32] = px;
        g_k[base + 33] = py;
        g_k[base + 34] = pz;
        g_k[base + 35] = -p2;
    }
}

// =============================================================================
// Attention: one thread per (b,h,query), packed f32x2 math throughout.
// Logits bounded above so no max-tracking is needed (plain exp-sum).
// 128 threads/CTA, grid (16, 16) = 256 CTAs.
// =============================================================================
__global__ void __launch_bounds__(128)
attn_kernel() {
    const int tid  = threadIdx.x;
    const int bh   = blockIdx.y;                 // 0..15
    const int qrow = blockIdx.x * 128 + tid;

    // load augmented query as 18 packed f32x2
    const ulonglong2* qp = (const ulonglong2*)(g_q + ((size_t)bh*NN + qrow) * DA);
    u64 q2[18];
    #pragma unroll
    for (int t = 0; t < 9; t++) {
        ulonglong2 u = qp[t];
        q2[2*t]   = u.x;
        q2[2*t+1] = u.y;
    }

    u64 acc2[16];
    #pragma unroll
    for (int d = 0; d < 16; d++) acc2[d] = 0ull;
    float l = 0.f;

    __shared__ __align__(16) float sk[32 * DA];   // 4608 B
    __shared__ __align__(16) float sv[32 * HD];   // 4096 B

    const float4* kb = (const float4*)(g_k + (size_t)bh * NN * DA);
    const float4* vb = (const float4*)(g_v + (size_t)bh * NN * HD);

    for (int kt = 0; kt < NN/32; kt++) {
        __syncthreads();
        #pragma unroll
        for (int i = tid; i < 288; i += 128)
            ((float4*)sk)[i] = kb[kt * 288 + i];
        #pragma unroll
        for (int i = tid; i < 256; i += 128)
            ((float4*)sv)[i] = vb[kt * 256 + i];
        __syncthreads();

        #pragma unroll 2
        for (int kk = 0; kk < 32; kk++) {
            const ulonglong2* kp = (const ulonglong2*)(sk + kk * DA);
            u64 dp0 = 0ull, dp1 = 0ull;
            #pragma unroll
            for (int t = 0; t < 9; t++) {
                ulonglong2 kv = kp[t];
                dp0 = ffma2(q2[2*t],   kv.x, dp0);
                dp1 = ffma2(q2[2*t+1], kv.y, dp1);
            }
            float2 s0 = unpack2(dp0);
            float2 s1 = unpack2(dp1);
            float p = __expf((s0.x + s0.y) + (s1.x + s1.y));
            l += p;
            u64 pd = pack2(p, p);
            const ulonglong2* vp = (const ulonglong2*)(sv + kk * HD);
            #pragma unroll
            for (int t = 0; t < 8; t++) {
                ulonglong2 vv = vp[t];
                acc2[2*t]   = ffma2(pd, vv.x, acc2[2*t]);
                acc2[2*t+1] = ffma2(pd, vv.y, acc2[2*t+1]);
            }
        }
    }

    float inv = 1.f / l;
    u64 invd = pack2(inv, inv);
    int b = bh >> 3;
    int h = bh & 7;
    ulonglong2* op = (ulonglong2*)(g_att + ((size_t)(b*NN + qrow)) * CC + h * HD);
    #pragma unroll
    for (int t = 0; t < 8; t++) {
        ulonglong2 o;
        o.x = fmul2(acc2[2*t],   invd);
        o.y = fmul2(acc2[2*t+1], invd);
        op[t] = o;
    }
}

// =============================================================================
// Residual + LayerNorm: out = LN(feature + g_o) * g + b
// =============================================================================
__global__ void __launch_bounds__(256)
ln_kernel(const float* __restrict__ feat,
          const float* __restrict__ ln_g, const float* __restrict__ ln_b,
          float* __restrict__ out) {
    const int m = blockIdx.x;
    const int c = threadIdx.x;
    float f = feat[(size_t)m*CC + c] + g_o[(size_t)m*CC + c];

    __shared__ float red[256];
    red[c] = f;
    __syncthreads();
    #pragma unroll
    for (int s = 128; s > 0; s >>= 1) {
        if (c < s) red[c] += red[c + s];
        __syncthreads();
    }
    float mu = red[0] * (1.f/256.f);
    __syncthreads();

    float d = f - mu;
    red[c] = d * d;
    __syncthreads();
    #pragma unroll
    for (int s = 128; s > 0; s >>= 1) {
        if (c < s) red[c] += red[c + s];
        __syncthreads();
    }
    float var = red[0] * (1.f/256.f);

    out[(size_t)m*CC + c] = d * rsqrtf(var + 1e-5f) * ln_g[c] + ln_b[c];
}

// =============================================================================
extern "C" void kernel_launch(void* const* d_in, const int* in_sizes, int n_in,
                              void* d_out, int out_size) {
    const float* feature = (const float*)d_in[0];
    const float* points  = (const float*)d_in[1];
    const float* Wq = (const float*)d_in[2];
    const float* bq = (const float*)d_in[3];
    const float* Wk = (const float*)d_in[4];
    const float* bk = (const float*)d_in[5];
    const float* Wv = (const float*)d_in[6];
    const float* bv = (const float*)d_in[7];
    const float* Wo = (const float*)d_in[8];
    const float* bo = (const float*)d_in[9];
    const float* ln_g = (const float*)d_in[10];
    const float* ln_b = (const float*)d_in[11];
    float* out = (float*)d_out;

    dim3 gq(M_TOT/64, CC/64, 3);            // 64 x 4 x 3 = 768 blocks
    gemm_qkv<<<gq, 256>>>(feature, Wq, Wk, Wv, bq, bk, bv);

    pack_points<<<(M_TOT + 255)/256, 256>>>(points);

    dim3 ga(NN/128, BB*HH);                 // 16 x 16 = 256 blocks
    attn_kernel<<<ga, 128>>>();

    dim3 go(M_TOT/64, CC/64);               // 64 x 4 = 256 blocks
    gemm_o<<<go, 256>>>(Wo, bo);

    ln_kernel<<<M_TOT, 256>>>(feature, ln_g, ln_b, out);
}

// round 5
// speedup vs baseline: 2.6569x; 2.4173x over previous
#include <cuda_runtime.h>
#include <cuda_bf16.h>
#include <cstdint>

#define BB 2
#define NN 2048
#define CC 256
#define HH 8
#define HD 32
#define DA 36
#define M_TOT (BB*NN)
#define QK_SCALE 0.17677669529663687f
#define LOG2E 1.4426950408889634f

typedef unsigned long long u64;

// ---------------- scratch (static device memory) -----------------------------
__device__ float g_q[(size_t)BB*HH*NN*DA];
__device__ float g_k[(size_t)BB*HH*NN*DA];
__device__ float g_v[(size_t)BB*HH*NN*HD];
__device__ float g_att[(size_t)M_TOT*CC];
__device__ float g_o[(size_t)M_TOT*CC];
// packed bf16 operands for mma path: rows of 120 (Q,K) / 40 (V) bf16
__device__ uint4 g_qt[(size_t)16*NN*15];   // [bh][n][120 bf16] = [qhi|qhi|qlo|pad]
__device__ uint4 g_ktp[(size_t)16*NN*15];  // [bh][n][120 bf16] = [khi|klo|khi|pad]
__device__ uint4 g_vtp[(size_t)16*NN*5];   // [bh][n][40 bf16]  = [v|pad]

// ---------------- packed f32x2 helpers ---------------------------------------
__device__ __forceinline__ u64 ffma2(u64 a, u64 b, u64 c) {
    u64 d; asm("fma.rn.f32x2 %0, %1, %2, %3;" : "=l"(d) : "l"(a), "l"(b), "l"(c)); return d;
}
__device__ __forceinline__ u64 pack2(float lo, float hi) {
    u64 r; asm("mov.b64 %0, {%1, %2};" : "=l"(r) : "f"(lo), "f"(hi)); return r;
}
__device__ __forceinline__ float2 unpack2(u64 v) {
    float lo, hi; asm("mov.b64 {%0, %1}, %2;" : "=f"(lo), "=f"(hi) : "l"(v)); return make_float2(lo, hi);
}
__device__ __forceinline__ uint32_t smem_u32(const void* p) {
    uint32_t a;
    asm("{ .reg .u64 t; cvta.to.shared.u64 t, %1; cvt.u32.u64 %0, t; }" : "=r"(a) : "l"(p));
    return a;
}

// ---------------- mma / ldmatrix helpers (sm_80+ portable) --------------------
#define LDSM_X4(r, a) \
    asm volatile("ldmatrix.sync.aligned.m8n8.x4.shared.b16 {%0,%1,%2,%3}, [%4];" \
        : "=r"((r)[0]), "=r"((r)[1]), "=r"((r)[2]), "=r"((r)[3]) : "r"(a))
#define LDSM_X2(r, a) \
    asm volatile("ldmatrix.sync.aligned.m8n8.x2.shared.b16 {%0,%1}, [%2];" \
        : "=r"((r)[0]), "=r"((r)[1]) : "r"(a))
#define LDSM_X4T(r, a) \
    asm volatile("ldmatrix.sync.aligned.m8n8.x4.trans.shared.b16 {%0,%1,%2,%3}, [%4];" \
        : "=r"((r)[0]), "=r"((r)[1]), "=r"((r)[2]), "=r"((r)[3]) : "r"(a))
#define MMA16816(d, a, b0, b1) \
    asm volatile("mma.sync.aligned.m16n8k16.row.col.f32.bf16.bf16.f32 " \
        "{%0,%1,%2,%3}, {%4,%5,%6,%7}, {%8,%9}, {%0,%1,%2,%3};" \
        : "+f"((d)[0]), "+f"((d)[1]), "+f"((d)[2]), "+f"((d)[3]) \
        : "r"((a)[0]), "r"((a)[1]), "r"((a)[2]), "r"((a)[3]), "r"(b0), "r"(b1))
#define CP_ASYNC16(dst_u32, src) \
    asm volatile("cp.async.cg.shared.global [%0], [%1], 16;" :: "r"(dst_u32), "l"(src))
#define CP_COMMIT() asm volatile("cp.async.commit_group;" ::: "memory")
#define CP_WAIT(n)  asm volatile("cp.async.wait_group %0;" :: "n"(n) : "memory")

// =============================================================================
// SGEMM (64x64, f32x2) — unchanged (passing since round 2)
// =============================================================================
__device__ __forceinline__ void gemm64_mainloop(const float* __restrict__ A,
                                                const float* __restrict__ W,
                                                int r0, int c0, u64 acc2[2][4]) {
    __shared__ __align__(16) float As[16][68];
    __shared__ __align__(16) float Bs[16][64];
    const int tid = threadIdx.x;
    const int tx = tid & 15;
    const int ty = tid >> 4;
    const int arow = tid >> 2;
    const int acg  = tid & 3;
    const int brow = tid >> 4;
    const int bcol = (tid & 15) * 4;

    for (int kk = 0; kk < CC; kk += 16) {
        float4 av = *(const float4*)(A + (size_t)(r0 + arow) * CC + kk + acg * 4);
        As[acg*4 + 0][arow] = av.x; As[acg*4 + 1][arow] = av.y;
        As[acg*4 + 2][arow] = av.z; As[acg*4 + 3][arow] = av.w;
        *(float4*)&Bs[brow][bcol] = *(const float4*)(W + (size_t)(kk + brow) * CC + c0 + bcol);
        __syncthreads();
        #pragma unroll
        for (int k = 0; k < 16; k++) {
            ulonglong2 a2 = *(const ulonglong2*)&As[k][ty*4];
            float4 b4 = *(const float4*)&Bs[k][tx*4];
            u64 b0 = pack2(b4.x, b4.x), b1 = pack2(b4.y, b4.y);
            u64 b2 = pack2(b4.z, b4.z), b3 = pack2(b4.w, b4.w);
            acc2[0][0] = ffma2(a2.x, b0, acc2[0][0]);
            acc2[0][1] = ffma2(a2.x, b1, acc2[0][1]);
            acc2[0][2] = ffma2(a2.x, b2, acc2[0][2]);
            acc2[0][3] = ffma2(a2.x, b3, acc2[0][3]);
            acc2[1][0] = ffma2(a2.y, b0, acc2[1][0]);
            acc2[1][1] = ffma2(a2.y, b1, acc2[1][1]);
            acc2[1][2] = ffma2(a2.y, b2, acc2[1][2]);
            acc2[1][3] = ffma2(a2.y, b3, acc2[1][3]);
        }
        __syncthreads();
    }
}

__global__ void __launch_bounds__(256)
gemm_qkv(const float* __restrict__ feat,
         const float* __restrict__ Wq, const float* __restrict__ Wk,
         const float* __restrict__ Wv,
         const float* __restrict__ bq, const float* __restrict__ bk,
         const float* __restrict__ bv) {
    const int z  = blockIdx.z;
    const int r0 = blockIdx.x * 64;
    const int c0 = blockIdx.y * 64;
    const float* W    = (z == 0) ? Wq : (z == 1) ? Wk : Wv;
    const float* bias = (z == 0) ? bq : (z == 1) ? bk : bv;

    u64 acc2[2][4];
    #pragma unroll
    for (int i = 0; i < 2; i++)
        #pragma unroll
        for (int j = 0; j < 4; j++) acc2[i][j] = 0ull;
    gemm64_mainloop(feat, W, r0, c0, acc2);

    const int tx = threadIdx.x & 15;
    const int ty = threadIdx.x >> 4;
    #pragma unroll
    for (int ip = 0; ip < 2; ip++) {
        #pragma unroll
        for (int j = 0; j < 4; j++) {
            float2 f = unpack2(acc2[ip][j]);
            int c = c0 + tx*4 + j;
            int h = c >> 5, d = c & 31;
            float bcol = bias[c];
            #pragma unroll
            for (int half = 0; half < 2; half++) {
                int m = r0 + ty*4 + ip*2 + half;
                int b = m >> 11, n = m & (NN - 1);
                float val = (half ? f.y : f.x) + bcol;
                size_t idx = (((size_t)b*HH + h)*NN + n);
                if (z == 0)       g_q[idx*DA + d] = val * QK_SCALE;
                else if (z == 1)  g_k[idx*DA + d] = val;
                else              g_v[idx*HD + d] = val;
            }
        }
    }
}

__global__ void __launch_bounds__(256)
gemm_o(const float* __restrict__ Wo, const float* __restrict__ bo) {
    const int r0 = blockIdx.x * 64;
    const int c0 = blockIdx.y * 64;
    u64 acc2[2][4];
    #pragma unroll
    for (int i = 0; i < 2; i++)
        #pragma unroll
        for (int j = 0; j < 4; j++) acc2[i][j] = 0ull;
    gemm64_mainloop(g_att, Wo, r0, c0, acc2);

    const int tx = threadIdx.x & 15;
    const int ty = threadIdx.x >> 4;
    #pragma unroll
    for (int ip = 0; ip < 2; ip++) {
        #pragma unroll
        for (int j = 0; j < 4; j++) {
            float2 f = unpack2(acc2[ip][j]);
            int c = c0 + tx*4 + j;
            float bc = bo[c];
            int m0 = r0 + ty*4 + ip*2;
            g_o[(size_t)m0*CC + c]     = f.x + bc;
            g_o[(size_t)(m0+1)*CC + c] = f.y + bc;
        }
    }
}

// =============================================================================
// pack_points — fill augmented dims (q~: 2p,1 ; k~: p,-|p|^2)
// =============================================================================
__global__ void pack_points(const float* __restrict__ pts) {
    int m = blockIdx.x * blockDim.x + threadIdx.x;
    if (m >= M_TOT) return;
    int b = m >> 11, n = m & (NN - 1);
    float px = pts[m*3+0], py = pts[m*3+1], pz = pts[m*3+2];
    float p2 = px*px + py*py + pz*pz;
    #pragma unroll
    for (int h = 0; h < HH; h++) {
        size_t base = (((size_t)b*HH + h)*NN + n) * DA;
        g_q[base+32] = 2.f*px; g_q[base+33] = 2.f*py;
        g_q[base+34] = 2.f*pz; g_q[base+35] = 1.f;
        g_k[base+32] = px; g_k[base+33] = py;
        g_k[base+34] = pz; g_k[base+35] = -p2;
    }
}

// =============================================================================
// conv_pack: build bf16 operand rows.
//   Q row (scaled by LOG2E): [hi(36) | hi(36) | lo(36) | 0(12)]   -> g_qt
//   K row:                   [hi(36) | lo(36) | hi(36) | 0(12)]   -> g_ktp
//   V row:                   [v(32) | 0(8)]                        -> g_vtp
// thread = (bh, n)
// =============================================================================
__global__ void __launch_bounds__(256)
conv_pack() {
    int t = blockIdx.x * 256 + threadIdx.x;
    if (t >= 16*NN) return;

    // ---- Q
    {
        const float* src = g_q + (size_t)t * DA;
        unsigned short hi[36], lo[36];
        #pragma unroll
        for (int i = 0; i < 36; i++) {
            float v = src[i] * LOG2E;
            __nv_bfloat16 h = __float2bfloat16(v);
            __nv_bfloat16 l = __float2bfloat16(v - __bfloat162float(h));
            hi[i] = *(unsigned short*)&h;
            lo[i] = *(unsigned short*)&l;
        }
        uint4* dst = g_qt + (size_t)t * 15;
        #pragma unroll
        for (int j = 0; j < 15; j++) {
            unsigned short e[8];
            #pragma unroll
            for (int u = 0; u < 8; u++) {
                int c = j*8 + u;
                e[u] = (c < 36) ? hi[c] : (c < 72) ? hi[c-36] : (c < 108) ? lo[c-72] : (unsigned short)0;
            }
            uint4 w;
            w.x = (uint32_t)e[0] | ((uint32_t)e[1] << 16);
            w.y = (uint32_t)e[2] | ((uint32_t)e[3] << 16);
            w.z = (uint32_t)e[4] | ((uint32_t)e[5] << 16);
            w.w = (uint32_t)e[6] | ((uint32_t)e[7] << 16);
            dst[j] = w;
        }
    }
    // ---- K
    {
        const float* src = g_k + (size_t)t * DA;
        unsigned short hi[36], lo[36];
        #pragma unroll
        for (int i = 0; i < 36; i++) {
            float v = src[i];
            __nv_bfloat16 h = __float2bfloat16(v);
            __nv_bfloat16 l = __float2bfloat16(v - __bfloat162float(h));
            hi[i] = *(unsigned short*)&h;
            lo[i] = *(unsigned short*)&l;
        }
        uint4* dst = g_ktp + (size_t)t * 15;
        #pragma unroll
        for (int j = 0; j < 15; j++) {
            unsigned short e[8];
            #pragma unroll
            for (int u = 0; u < 8; u++) {
                int c = j*8 + u;
                e[u] = (c < 36) ? hi[c] : (c < 72) ? lo[c-36] : (c < 108) ? hi[c-72] : (unsigned short)0;
            }
            uint4 w;
            w.x = (uint32_t)e[0] | ((uint32_t)e[1] << 16);
            w.y = (uint32_t)e[2] | ((uint32_t)e[3] << 16);
            w.z = (uint32_t)e[4] | ((uint32_t)e[5] << 16);
            w.w = (uint32_t)e[6] | ((uint32_t)e[7] << 16);
            dst[j] = w;
        }
    }
    // ---- V
    {
        const float* src = g_v + (size_t)t * HD;
        uint4* dst = g_vtp + (size_t)t * 5;
        #pragma unroll
        for (int j = 0; j < 5; j++) {
            unsigned short e[8];
            #pragma unroll
            for (int u = 0; u < 8; u++) {
                int c = j*8 + u;
                if (c < 32) {
                    __nv_bfloat16 h = __float2bfloat16(src[c]);
                    e[u] = *(unsigned short*)&h;
                } else e[u] = 0;
            }
            uint4 w;
            w.x = (uint32_t)e[0] | ((uint32_t)e[1] << 16);
            w.y = (uint32_t)e[2] | ((uint32_t)e[3] << 16);
            w.z = (uint32_t)e[4] | ((uint32_t)e[5] << 16);
            w.w = (uint32_t)e[6] | ((uint32_t)e[7] << 16);
            dst[j] = w;
        }
    }
}

// =============================================================================
// attn_mma: flash attention with mma.sync m16n8k16 bf16.
// CTA = (qtile of 128 rows, bh). 8 warps x 16 rows. 64-key tiles, cp.async
// double-buffered. S fragments stay in registers; C->A fragment pairing for P.
// =============================================================================
#define KROW 120   // bf16 per K/Q row (240 B)
#define VROW 40    // bf16 per V row (80 B)

__global__ void __launch_bounds__(256, 2)
attn_mma() {
    __shared__ __align__(16) unsigned short sK[2][64*KROW];  // 2 x 15360 B
    __shared__ __align__(16) unsigned short sV[2][64*VROW];  // 2 x 5120 B

    const int tid  = threadIdx.x;
    const int lane = tid & 31;
    const int wid  = tid >> 5;
    const int bh = blockIdx.y;
    const int qt = blockIdx.x;
    const int b = bh >> 3, h = bh & 7;

    // ---- stage Q (128 rows x 240B = 30720B) into sK[0]+sK[1] (contiguous)
    {
        const uint4* src = g_qt + ((size_t)bh*NN + qt*128) * 15;
        uint4* dst = (uint4*)&sK[0][0];
        for (int i = tid; i < 1920; i += 256) dst[i] = src[i];
    }
    __syncthreads();

    // ---- load Q fragments: 7 k16-chunks, one ldmatrix.x4 each
    uint32_t qa[7][4];
    {
        uint32_t qbase = smem_u32(&sK[0][0]) + (wid*16 + (lane & 15))*240 + (lane >> 4)*16;
        #pragma unroll
        for (int c = 0; c < 7; c++) LDSM_X4(qa[c], qbase + c*32);
    }
    __syncthreads();   // Q regs loaded; sK reusable

    float oc[4][4];
    #pragma unroll
    for (int i = 0; i < 4; i++)
        #pragma unroll
        for (int j = 0; j < 4; j++) oc[i][j] = 0.f;
    float ls0 = 0.f, ls1 = 0.f;

    const uint4* kg_src = g_ktp + (size_t)bh*NN*15;
    const uint4* vg_src = g_vtp + (size_t)bh*NN*5;

    // prefetch tile 0
    {
        uint32_t kd = smem_u32(&sK[0][0]);
        uint32_t vd = smem_u32(&sV[0][0]);
        const uint4* ks = kg_src;
        const uint4* vs = vg_src;
        for (int i = tid; i < 960; i += 256) CP_ASYNC16(kd + i*16, ks + i);
        for (int i = tid; i < 320; i += 256) CP_ASYNC16(vd + i*16, vs + i);
        CP_COMMIT();
    }

    for (int t = 0; t < 32; t++) {
        if (t < 31) {
            int nb = (t + 1) & 1;
            uint32_t kd = smem_u32(&sK[nb][0]);
            uint32_t vd = smem_u32(&sV[nb][0]);
            const uint4* ks = kg_src + (size_t)(t+1)*64*15;
            const uint4* vs = vg_src + (size_t)(t+1)*64*5;
            for (int i = tid; i < 960; i += 256) CP_ASYNC16(kd + i*16, ks + i);
            for (int i = tid; i < 320; i += 256) CP_ASYNC16(vd + i*16, vs + i);
            CP_COMMIT();
            CP_WAIT(1);
        } else {
            CP_WAIT(0);
        }
        __syncthreads();

        const int buf = t & 1;
        uint32_t kbase = smem_u32(&sK[buf][0]);
        uint32_t vbase = smem_u32(&sV[buf][0]);

        // ---- S = Q~ K~^T  (8 n-tiles of 8 keys)
        float sc[8][4];
        #pragma unroll
        for (int kg = 0; kg < 8; kg++) {
            #pragma unroll
            for (int j = 0; j < 4; j++) sc[kg][j] = 0.f;
            uint32_t kb[14];
            uint32_t ka = kbase + (kg*8 + (lane & 7))*240 + ((lane >> 3) & 3)*16;
            LDSM_X4(&kb[0], ka);
            LDSM_X4(&kb[4], ka + 64);
            LDSM_X4(&kb[8], ka + 128);
            uint32_t ka2 = kbase + (kg*8 + (lane & 7))*240 + 192 + ((lane >> 3) & 1)*16;
            LDSM_X2(&kb[12], ka2);
            #pragma unroll
            for (int c = 0; c < 7; c++)
                MMA16816(sc[kg], qa[c], kb[2*c], kb[2*c+1]);
        }

        // ---- softmax (exp2; row-sum accumulate) -> P A-fragments
        uint32_t pa[4][4];
        #pragma unroll
        for (int pc = 0; pc < 4; pc++) {
            float e[8];
            #pragma unroll
            for (int half = 0; half < 2; half++) {
                const float* s = sc[2*pc + half];
                #pragma unroll
                for (int j = 0; j < 4; j++)
                    asm("ex2.approx.f32 %0, %1;" : "=f"(e[half*4 + j]) : "f"(s[j]));
            }
            ls0 += (e[0] + e[1]) + (e[4] + e[5]);
            ls1 += (e[2] + e[3]) + (e[6] + e[7]);
            asm("cvt.rn.bf16x2.f32 %0, %1, %2;" : "=r"(pa[pc][0]) : "f"(e[1]), "f"(e[0]));
            asm("cvt.rn.bf16x2.f32 %0, %1, %2;" : "=r"(pa[pc][1]) : "f"(e[3]), "f"(e[2]));
            asm("cvt.rn.bf16x2.f32 %0, %1, %2;" : "=r"(pa[pc][2]) : "f"(e[5]), "f"(e[4]));
            asm("cvt.rn.bf16x2.f32 %0, %1, %2;" : "=r"(pa[pc][3]) : "f"(e[7]), "f"(e[6]));
        }

        // ---- O += P V   (keys contract 64 = 4 k-chunks; hd 32 = 4 n-tiles)
        #pragma unroll
        for (int hp = 0; hp < 2; hp++) {
            #pragma unroll
            for (int pc = 0; pc < 4; pc++) {
                uint32_t vb[4];
                uint32_t va = vbase + (pc*16 + (lane & 15))*80 + hp*32 + (lane >> 4)*16;
                LDSM_X4T(vb, va);
                MMA16816(oc[2*hp],     pa[pc], vb[0], vb[1]);
                MMA16816(oc[2*hp + 1], pa[pc], vb[2], vb[3]);
            }
        }
        __syncthreads();
    }

    // ---- quad reduction of row sums (lanes 4g..4g+3 share rows g, g+8)
    ls0 += __shfl_xor_sync(0xFFFFFFFFu, ls0, 1);
    ls0 += __shfl_xor_sync(0xFFFFFFFFu, ls0, 2);
    ls1 += __shfl_xor_sync(0xFFFFFFFFu, ls1, 1);
    ls1 += __shfl_xor_sync(0xFFFFFFFFu, ls1, 2);
    float inv0 = 1.f / ls0;
    float inv1 = 1.f / ls1;

    const int g  = lane >> 2;
    const int tq = lane & 3;
    const int row0 = qt*128 + wid*16 + g;
    float* base = g_att + ((size_t)(b*NN + row0))*CC + h*HD;
    #pragma unroll
    for (int n = 0; n < 4; n++) {
        *(float2*)(base + n*8 + 2*tq)          = make_float2(oc[n][0]*inv0, oc[n][1]*inv0);
        *(float2*)(base + (size_t)8*CC + n*8 + 2*tq) = make_float2(oc[n][2]*inv1, oc[n][3]*inv1);
    }
}

// =============================================================================
// Residual + LayerNorm
// =============================================================================
__global__ void __launch_bounds__(256)
ln_kernel(const float* __restrict__ feat,
          const float* __restrict__ ln_g, const float* __restrict__ ln_b,
          float* __restrict__ out) {
    const int m = blockIdx.x;
    const int c = threadIdx.x;
    float f = feat[(size_t)m*CC + c] + g_o[(size_t)m*CC + c];

    __shared__ float red[256];
    red[c] = f;
    __syncthreads();
    #pragma unroll
    for (int s = 128; s > 0; s >>= 1) {
        if (c < s) red[c] += red[c + s];
        __syncthreads();
    }
    float mu = red[0] * (1.f/256.f);
    __syncthreads();
    float d = f - mu;
    red[c] = d * d;
    __syncthreads();
    #pragma unroll
    for (int s = 128; s > 0; s >>= 1) {
        if (c < s) red[c] += red[c + s];
        __syncthreads();
    }
    float var = red[0] * (1.f/256.f);
    out[(size_t)m*CC + c] = d * rsqrtf(var + 1e-5f) * ln_g[c] + ln_b[c];
}

// =============================================================================
extern "C" void kernel_launch(void* const* d_in, const int* in_sizes, int n_in,
                              void* d_out, int out_size) {
    const float* feature = (const float*)d_in[0];
    const float* points  = (const float*)d_in[1];
    const float* Wq = (const float*)d_in[2];
    const float* bq = (const float*)d_in[3];
    const float* Wk = (const float*)d_in[4];
    const float* bk = (const float*)d_in[5];
    const float* Wv = (const float*)d_in[6];
    const float* bv = (const float*)d_in[7];
    const float* Wo = (const float*)d_in[8];
    const float* bo = (const float*)d_in[9];
    const float* ln_g = (const float*)d_in[10];
    const float* ln_b = (const float*)d_in[11];
    float* out = (float*)d_out;

    dim3 gq(M_TOT/64, CC/64, 3);
    gemm_qkv<<<gq, 256>>>(feature, Wq, Wk, Wv, bq, bk, bv);

    pack_points<<<(M_TOT + 255)/256, 256>>>(points);

    conv_pack<<<(16*NN)/256, 256>>>();

    dim3 ga(16, 16);
    attn_mma<<<ga, 256>>>();

    dim3 go(M_TOT/64, CC/64);
    gemm_o<<<go, 256>>>(Wo, bo);

    ln_kernel<<<M_TOT, 256>>>(feature, ln_g, ln_b, out);
}

// round 6
// speedup vs baseline: 3.1274x; 1.1771x over previous
#include <cuda_runtime.h>
#include <cuda_bf16.h>
#include <cstdint>

#define BB 2
#define NN 2048
#define CC 256
#define HH 8
#define HD 32
#define M_TOT (BB*NN)
#define QK_SCALE 0.17677669529663687f
#define LOG2E 1.4426950408889634f

typedef unsigned long long u64;

// ---------------- scratch (static device memory) -----------------------------
__device__ float g_q[(size_t)BB*HH*NN*HD];   // [bh][n][32] scaled by QK_SCALE
__device__ float g_k[(size_t)BB*HH*NN*HD];   // [bh][n][32]
__device__ float g_v[(size_t)BB*HH*NN*HD];
__device__ float g_att[(size_t)M_TOT*CC];
__device__ float g_o[(size_t)M_TOT*CC];
// packed bf16 operand rows (88 bf16 = 176B for Q/K, 40 bf16 = 80B for V)
__device__ uint4 g_qt[(size_t)16*NN*11];   // [bh][n][88] = [qhi(36)|qlo(36)|0(16)] *LOG2E
__device__ uint4 g_ktp[(size_t)16*NN*11];  // [bh][n][88] = [khi(36)|khi(36)|0(16)]
__device__ uint4 g_vtp[(size_t)16*NN*5];   // [bh][n][40] = [v(32)|0(8)]

// ---------------- packed f32x2 helpers ---------------------------------------
__device__ __forceinline__ u64 ffma2(u64 a, u64 b, u64 c) {
    u64 d; asm("fma.rn.f32x2 %0, %1, %2, %3;" : "=l"(d) : "l"(a), "l"(b), "l"(c)); return d;
}
__device__ __forceinline__ u64 pack2(float lo, float hi) {
    u64 r; asm("mov.b64 %0, {%1, %2};" : "=l"(r) : "f"(lo), "f"(hi)); return r;
}
__device__ __forceinline__ float2 unpack2(u64 v) {
    float lo, hi; asm("mov.b64 {%0, %1}, %2;" : "=f"(lo), "=f"(hi) : "l"(v)); return make_float2(lo, hi);
}
__device__ __forceinline__ uint32_t smem_u32(const void* p) {
    uint32_t a;
    asm("{ .reg .u64 t; cvta.to.shared.u64 t, %1; cvt.u32.u64 %0, t; }" : "=r"(a) : "l"(p));
    return a;
}

// ---------------- mma / ldmatrix helpers (sm_80+ portable) --------------------
#define LDSM_X4(r, a) \
    asm volatile("ldmatrix.sync.aligned.m8n8.x4.shared.b16 {%0,%1,%2,%3}, [%4];" \
        : "=r"((r)[0]), "=r"((r)[1]), "=r"((r)[2]), "=r"((r)[3]) : "r"(a))
#define LDSM_X2(r, a) \
    asm volatile("ldmatrix.sync.aligned.m8n8.x2.shared.b16 {%0,%1}, [%2];" \
        : "=r"((r)[0]), "=r"((r)[1]) : "r"(a))
#define LDSM_X4T(r, a) \
    asm volatile("ldmatrix.sync.aligned.m8n8.x4.trans.shared.b16 {%0,%1,%2,%3}, [%4];" \
        : "=r"((r)[0]), "=r"((r)[1]), "=r"((r)[2]), "=r"((r)[3]) : "r"(a))
#define MMA16816(d, a, b0, b1) \
    asm volatile("mma.sync.aligned.m16n8k16.row.col.f32.bf16.bf16.f32 " \
        "{%0,%1,%2,%3}, {%4,%5,%6,%7}, {%8,%9}, {%0,%1,%2,%3};" \
        : "+f"((d)[0]), "+f"((d)[1]), "+f"((d)[2]), "+f"((d)[3]) \
        : "r"((a)[0]), "r"((a)[1]), "r"((a)[2]), "r"((a)[3]), "r"(b0), "r"(b1))
#define CP_ASYNC16(dst_u32, src) \
    asm volatile("cp.async.cg.shared.global [%0], [%1], 16;" :: "r"(dst_u32), "l"(src))
#define CP_COMMIT() asm volatile("cp.async.commit_group;" ::: "memory")
#define CP_WAIT(n)  asm volatile("cp.async.wait_group %0;" :: "n"(n) : "memory")

// =============================================================================
// SGEMM (64x64, f32x2) — unchanged (passing since round 2)
// =============================================================================
__device__ __forceinline__ void gemm64_mainloop(const float* __restrict__ A,
                                                const float* __restrict__ W,
                                                int r0, int c0, u64 acc2[2][4]) {
    __shared__ __align__(16) float As[16][68];
    __shared__ __align__(16) float Bs[16][64];
    const int tid = threadIdx.x;
    const int tx = tid & 15;
    const int ty = tid >> 4;
    const int arow = tid >> 2;
    const int acg  = tid & 3;
    const int brow = tid >> 4;
    const int bcol = (tid & 15) * 4;

    for (int kk = 0; kk < CC; kk += 16) {
        float4 av = *(const float4*)(A + (size_t)(r0 + arow) * CC + kk + acg * 4);
        As[acg*4 + 0][arow] = av.x; As[acg*4 + 1][arow] = av.y;
        As[acg*4 + 2][arow] = av.z; As[acg*4 + 3][arow] = av.w;
        *(float4*)&Bs[brow][bcol] = *(const float4*)(W + (size_t)(kk + brow) * CC + c0 + bcol);
        __syncthreads();
        #pragma unroll
        for (int k = 0; k < 16; k++) {
            ulonglong2 a2 = *(const ulonglong2*)&As[k][ty*4];
            float4 b4 = *(const float4*)&Bs[k][tx*4];
            u64 b0 = pack2(b4.x, b4.x), b1 = pack2(b4.y, b4.y);
            u64 b2 = pack2(b4.z, b4.z), b3 = pack2(b4.w, b4.w);
            acc2[0][0] = ffma2(a2.x, b0, acc2[0][0]);
            acc2[0][1] = ffma2(a2.x, b1, acc2[0][1]);
            acc2[0][2] = ffma2(a2.x, b2, acc2[0][2]);
            acc2[0][3] = ffma2(a2.x, b3, acc2[0][3]);
            acc2[1][0] = ffma2(a2.y, b0, acc2[1][0]);
            acc2[1][1] = ffma2(a2.y, b1, acc2[1][1]);
            acc2[1][2] = ffma2(a2.y, b2, acc2[1][2]);
            acc2[1][3] = ffma2(a2.y, b3, acc2[1][3]);
        }
        __syncthreads();
    }
}

__global__ void __launch_bounds__(256)
gemm_qkv(const float* __restrict__ feat,
         const float* __restrict__ Wq, const float* __restrict__ Wk,
         const float* __restrict__ Wv,
         const float* __restrict__ bq, const float* __restrict__ bk,
         const float* __restrict__ bv) {
    const int z  = blockIdx.z;
    const int r0 = blockIdx.x * 64;
    const int c0 = blockIdx.y * 64;
    const float* W    = (z == 0) ? Wq : (z == 1) ? Wk : Wv;
    const float* bias = (z == 0) ? bq : (z == 1) ? bk : bv;

    u64 acc2[2][4];
    #pragma unroll
    for (int i = 0; i < 2; i++)
        #pragma unroll
        for (int j = 0; j < 4; j++) acc2[i][j] = 0ull;
    gemm64_mainloop(feat, W, r0, c0, acc2);

    const int tx = threadIdx.x & 15;
    const int ty = threadIdx.x >> 4;
    #pragma unroll
    for (int ip = 0; ip < 2; ip++) {
        #pragma unroll
        for (int j = 0; j < 4; j++) {
            float2 f = unpack2(acc2[ip][j]);
            int c = c0 + tx*4 + j;
            int h = c >> 5, d = c & 31;
            float bcol = bias[c];
            #pragma unroll
            for (int half = 0; half < 2; half++) {
                int m = r0 + ty*4 + ip*2 + half;
                int b = m >> 11, n = m & (NN - 1);
                float val = (half ? f.y : f.x) + bcol;
                size_t idx = (((size_t)b*HH + h)*NN + n);
                if (z == 0)       g_q[idx*HD + d] = val * QK_SCALE;
                else if (z == 1)  g_k[idx*HD + d] = val;
                else              g_v[idx*HD + d] = val;
            }
        }
    }
}

__global__ void __launch_bounds__(256)
gemm_o(const float* __restrict__ Wo, const float* __restrict__ bo) {
    const int r0 = blockIdx.x * 64;
    const int c0 = blockIdx.y * 64;
    u64 acc2[2][4];
    #pragma unroll
    for (int i = 0; i < 2; i++)
        #pragma unroll
        for (int j = 0; j < 4; j++) acc2[i][j] = 0ull;
    gemm64_mainloop(g_att, Wo, r0, c0, acc2);

    const int tx = threadIdx.x & 15;
    const int ty = threadIdx.x >> 4;
    #pragma unroll
    for (int ip = 0; ip < 2; ip++) {
        #pragma unroll
        for (int j = 0; j < 4; j++) {
            float2 f = unpack2(acc2[ip][j]);
            int c = c0 + tx*4 + j;
            float bc = bo[c];
            int m0 = r0 + ty*4 + ip*2;
            g_o[(size_t)m0*CC + c]     = f.x + bc;
            g_o[(size_t)(m0+1)*CC + c] = f.y + bc;
        }
    }
}

// =============================================================================
// conv_pack: build bf16 operand rows (aug dims computed inline from points).
//   Q row (x LOG2E): [qhi(36) | qlo(36) | 0(16)]  (aug: 2p, 1)      -> g_qt
//   K row:           [khi(36) | khi(36) | 0(16)]  (aug: p, -|p|^2)  -> g_ktp
//   V row:           [v(32) | 0(8)]                                  -> g_vtp
// thread = (bh, n). 2-term split: dot = q_hi*k_hi + q_lo*k_hi = q*k_hi.
// =============================================================================
__global__ void __launch_bounds__(256)
conv_pack(const float* __restrict__ pts) {
    int t = blockIdx.x * 256 + threadIdx.x;
    if (t >= 16*NN) return;
    int bh = t >> 11, n = t & (NN-1);
    int b = bh >> 3;
    int m = b*NN + n;
    float px = pts[m*3+0], py = pts[m*3+1], pz = pts[m*3+2];
    float p2 = px*px + py*py + pz*pz;

    // ---- Q: [hi|lo] of (q*LOG2E), aug dims {2p, 1}
    {
        const float* src = g_q + (size_t)t * HD;
        float qv[36];
        #pragma unroll
        for (int i = 0; i < 8; i++) {
            float4 f = *(const float4*)(src + 4*i);
            qv[4*i]   = f.x*LOG2E; qv[4*i+1] = f.y*LOG2E;
            qv[4*i+2] = f.z*LOG2E; qv[4*i+3] = f.w*LOG2E;
        }
        qv[32] = 2.f*px*LOG2E; qv[33] = 2.f*py*LOG2E;
        qv[34] = 2.f*pz*LOG2E; qv[35] = LOG2E;
        unsigned short hi[36], lo[36];
        #pragma unroll
        for (int i = 0; i < 36; i++) {
            __nv_bfloat16 h = __float2bfloat16(qv[i]);
            __nv_bfloat16 l = __float2bfloat16(qv[i] - __bfloat162float(h));
            hi[i] = *(unsigned short*)&h;
            lo[i] = *(unsigned short*)&l;
        }
        uint4* dst = g_qt + (size_t)t * 11;
        #pragma unroll
        for (int j = 0; j < 11; j++) {
            unsigned short e[8];
            #pragma unroll
            for (int u = 0; u < 8; u++) {
                int c = j*8 + u;
                e[u] = (c < 36) ? hi[c] : (c < 72) ? lo[c-36] : (unsigned short)0;
            }
            uint4 w;
            w.x = (uint32_t)e[0] | ((uint32_t)e[1] << 16);
            w.y = (uint32_t)e[2] | ((uint32_t)e[3] << 16);
            w.z = (uint32_t)e[4] | ((uint32_t)e[5] << 16);
            w.w = (uint32_t)e[6] | ((uint32_t)e[7] << 16);
            dst[j] = w;
        }
    }
    // ---- K: [hi|hi], aug dims {p, -|p|^2}
    {
        const float* src = g_k + (size_t)t * HD;
        float kv[36];
        #pragma unroll
        for (int i = 0; i < 8; i++) {
            float4 f = *(const float4*)(src + 4*i);
            kv[4*i] = f.x; kv[4*i+1] = f.y; kv[4*i+2] = f.z; kv[4*i+3] = f.w;
        }
        kv[32] = px; kv[33] = py; kv[34] = pz; kv[35] = -p2;
        unsigned short hi[36];
        #pragma unroll
        for (int i = 0; i < 36; i++) {
            __nv_bfloat16 h = __float2bfloat16(kv[i]);
            hi[i] = *(unsigned short*)&h;
        }
        uint4* dst = g_ktp + (size_t)t * 11;
        #pragma unroll
        for (int j = 0; j < 11; j++) {
            unsigned short e[8];
            #pragma unroll
            for (int u = 0; u < 8; u++) {
                int c = j*8 + u;
                e[u] = (c < 36) ? hi[c] : (c < 72) ? hi[c-36] : (unsigned short)0;
            }
            uint4 w;
            w.x = (uint32_t)e[0] | ((uint32_t)e[1] << 16);
            w.y = (uint32_t)e[2] | ((uint32_t)e[3] << 16);
            w.z = (uint32_t)e[4] | ((uint32_t)e[5] << 16);
            w.w = (uint32_t)e[6] | ((uint32_t)e[7] << 16);
            dst[j] = w;
        }
    }
    // ---- V
    {
        const float* src = g_v + (size_t)t * HD;
        uint4* dst = g_vtp + (size_t)t * 5;
        #pragma unroll
        for (int j = 0; j < 5; j++) {
            unsigned short e[8];
            #pragma unroll
            for (int u = 0; u < 8; u++) {
                int c = j*8 + u;
                if (c < 32) {
                    __nv_bfloat16 h = __float2bfloat16(src[c]);
                    e[u] = *(unsigned short*)&h;
                } else e[u] = 0;
            }
            uint4 w;
            w.x = (uint32_t)e[0] | ((uint32_t)e[1] << 16);
            w.y = (uint32_t)e[2] | ((uint32_t)e[3] << 16);
            w.z = (uint32_t)e[4] | ((uint32_t)e[5] << 16);
            w.w = (uint32_t)e[6] | ((uint32_t)e[7] << 16);
            dst[j] = w;
        }
    }
}

// =============================================================================
// attn_mma: flash attention with mma.sync m16n8k16 bf16, 2-term split.
// CTA = (qtile of 128 rows, bh). 8 warps x 16 rows. 64-key tiles, cp.async
// double-buffered. Contract = 80 (5 k16 chunks). Row stride 176B (conflict-free).
// =============================================================================
#define KROW 88    // bf16 per K/Q row (176 B)
#define VROW 40    // bf16 per V row (80 B)

__global__ void __launch_bounds__(256, 2)
attn_mma() {
    __shared__ __align__(16) unsigned short sK[2][64*KROW];  // 2 x 11264 B
    __shared__ __align__(16) unsigned short sV[2][64*VROW];  // 2 x 5120 B

    const int tid  = threadIdx.x;
    const int lane = tid & 31;
    const int wid  = tid >> 5;
    const int bh = blockIdx.y;
    const int qt = blockIdx.x;
    const int b = bh >> 3, h = bh & 7;

    // ---- stage Q (128 rows x 176B = 22528B) into sK[0]+sK[1] (contiguous)
    {
        const uint4* src = g_qt + ((size_t)bh*NN + qt*128) * 11;
        uint4* dst = (uint4*)&sK[0][0];
        for (int i = tid; i < 1408; i += 256) dst[i] = src[i];
    }
    __syncthreads();

    // ---- load Q fragments: 5 k16-chunks, one ldmatrix.x4 each
    uint32_t qa[5][4];
    {
        uint32_t qbase = smem_u32(&sK[0][0]) + (wid*16 + (lane & 15))*176 + (lane >> 4)*16;
        #pragma unroll
        for (int c = 0; c < 5; c++) LDSM_X4(qa[c], qbase + c*32);
    }
    __syncthreads();   // Q regs loaded; sK reusable

    float oc[4][4];
    #pragma unroll
    for (int i = 0; i < 4; i++)
        #pragma unroll
        for (int j = 0; j < 4; j++) oc[i][j] = 0.f;
    float ls0 = 0.f, ls1 = 0.f;

    const uint4* kg_src = g_ktp + (size_t)bh*NN*11;
    const uint4* vg_src = g_vtp + (size_t)bh*NN*5;

    // prefetch tile 0
    {
        uint32_t kd = smem_u32(&sK[0][0]);
        uint32_t vd = smem_u32(&sV[0][0]);
        for (int i = tid; i < 704; i += 256) CP_ASYNC16(kd + i*16, kg_src + i);
        for (int i = tid; i < 320; i += 256) CP_ASYNC16(vd + i*16, vg_src + i);
        CP_COMMIT();
    }

    for (int t = 0; t < 32; t++) {
        if (t < 31) {
            int nb = (t + 1) & 1;
            uint32_t kd = smem_u32(&sK[nb][0]);
            uint32_t vd = smem_u32(&sV[nb][0]);
            const uint4* ks = kg_src + (size_t)(t+1)*64*11;
            const uint4* vs = vg_src + (size_t)(t+1)*64*5;
            for (int i = tid; i < 704; i += 256) CP_ASYNC16(kd + i*16, ks + i);
            for (int i = tid; i < 320; i += 256) CP_ASYNC16(vd + i*16, vs + i);
            CP_COMMIT();
            CP_WAIT(1);
        } else {
            CP_WAIT(0);
        }
        __syncthreads();

        const int buf = t & 1;
        uint32_t kbase = smem_u32(&sK[buf][0]);
        uint32_t vbase = smem_u32(&sV[buf][0]);

        // ---- S = Q~ K~^T  (8 n-tiles of 8 keys, contract 80)
        float sc[8][4];
        #pragma unroll
        for (int kg = 0; kg < 8; kg++) {
            #pragma unroll
            for (int j = 0; j < 4; j++) sc[kg][j] = 0.f;
            uint32_t kb[10];
            uint32_t krow = kbase + (kg*8 + (lane & 7))*176;
            uint32_t ka = krow + ((lane >> 3) & 3)*16;
            LDSM_X4(&kb[0], ka);
            LDSM_X4(&kb[4], ka + 64);
            LDSM_X2(&kb[8], krow + 128 + ((lane >> 3) & 1)*16);
            #pragma unroll
            for (int c = 0; c < 5; c++)
                MMA16816(sc[kg], qa[c], kb[2*c], kb[2*c+1]);
        }

        // ---- softmax (exp2; row-sum accumulate) -> P A-fragments
        uint32_t pa[4][4];
        #pragma unroll
        for (int pc = 0; pc < 4; pc++) {
            float e[8];
            #pragma unroll
            for (int half = 0; half < 2; half++) {
                const float* s = sc[2*pc + half];
                #pragma unroll
                for (int j = 0; j < 4; j++)
                    asm("ex2.approx.f32 %0, %1;" : "=f"(e[half*4 + j]) : "f"(s[j]));
            }
            ls0 += (e[0] + e[1]) + (e[4] + e[5]);
            ls1 += (e[2] + e[3]) + (e[6] + e[7]);
            asm("cvt.rn.bf16x2.f32 %0, %1, %2;" : "=r"(pa[pc][0]) : "f"(e[1]), "f"(e[0]));
            asm("cvt.rn.bf16x2.f32 %0, %1, %2;" : "=r"(pa[pc][1]) : "f"(e[3]), "f"(e[2]));
            asm("cvt.rn.bf16x2.f32 %0, %1, %2;" : "=r"(pa[pc][2]) : "f"(e[5]), "f"(e[4]));
            asm("cvt.rn.bf16x2.f32 %0, %1, %2;" : "=r"(pa[pc][3]) : "f"(e[7]), "f"(e[6]));
        }

        // ---- O += P V   (keys contract 64 = 4 k-chunks; hd 32 = 4 n-tiles)
        #pragma unroll
        for (int hp = 0; hp < 2; hp++) {
            #pragma unroll
            for (int pc = 0; pc < 4; pc++) {
                uint32_t vb[4];
                uint32_t va = vbase + (pc*16 + (lane & 15))*80 + hp*32 + (lane >> 4)*16;
                LDSM_X4T(vb, va);
                MMA16816(oc[2*hp],     pa[pc], vb[0], vb[1]);
                MMA16816(oc[2*hp + 1], pa[pc], vb[2], vb[3]);
            }
        }
        __syncthreads();
    }

    // ---- quad reduction of row sums (lanes 4g..4g+3 share rows g, g+8)
    ls0 += __shfl_xor_sync(0xFFFFFFFFu, ls0, 1);
    ls0 += __shfl_xor_sync(0xFFFFFFFFu, ls0, 2);
    ls1 += __shfl_xor_sync(0xFFFFFFFFu, ls1, 1);
    ls1 += __shfl_xor_sync(0xFFFFFFFFu, ls1, 2);
    float inv0 = 1.f / ls0;
    float inv1 = 1.f / ls1;

    const int g  = lane >> 2;
    const int tq = lane & 3;
    const int row0 = qt*128 + wid*16 + g;
    float* base = g_att + ((size_t)(b*NN + row0))*CC + h*HD;
    #pragma unroll
    for (int n = 0; n < 4; n++) {
        *(float2*)(base + n*8 + 2*tq)                = make_float2(oc[n][0]*inv0, oc[n][1]*inv0);
        *(float2*)(base + (size_t)8*CC + n*8 + 2*tq) = make_float2(oc[n][2]*inv1, oc[n][3]*inv1);
    }
}

// =============================================================================
// Residual + LayerNorm
// =============================================================================
__global__ void __launch_bounds__(256)
ln_kernel(const float* __restrict__ feat,
          const float* __restrict__ ln_g, const float* __restrict__ ln_b,
          float* __restrict__ out) {
    const int m = blockIdx.x;
    const int c = threadIdx.x;
    float f = feat[(size_t)m*CC + c] + g_o[(size_t)m*CC + c];

    __shared__ float red[256];
    red[c] = f;
    __syncthreads();
    #pragma unroll
    for (int s = 128; s > 0; s >>= 1) {
        if (c < s) red[c] += red[c + s];
        __syncthreads();
    }
    float mu = red[0] * (1.f/256.f);
    __syncthreads();
    float d = f - mu;
    red[c] = d * d;
    __syncthreads();
    #pragma unroll
    for (int s = 128; s > 0; s >>= 1) {
        if (c < s) red[c] += red[c + s];
        __syncthreads();
    }
    float var = red[0] * (1.f/256.f);
    out[(size_t)m*CC + c] = d * rsqrtf(var + 1e-5f) * ln_g[c] + ln_b[c];
}

// =============================================================================
extern "C" void kernel_launch(void* const* d_in, const int* in_sizes, int n_in,
                              void* d_out, int out_size) {
    const float* feature = (const float*)d_in[0];
    const float* points  = (const float*)d_in[1];
    const float* Wq = (const float*)d_in[2];
    const float* bq = (const float*)d_in[3];
    const float* Wk = (const float*)d_in[4];
    const float* bk = (const float*)d_in[5];
    const float* Wv = (const float*)d_in[6];
    const float* bv = (const float*)d_in[7];
    const float* Wo = (const float*)d_in[8];
    const float* bo = (const float*)d_in[9];
    const float* ln_g = (const float*)d_in[10];
    const float* ln_b = (const float*)d_in[11];
    float* out = (float*)d_out;

    dim3 gq(M_TOT/64, CC/64, 3);
    gemm_qkv<<<gq, 256>>>(feature, Wq, Wk, Wv, bq, bk, bv);

    conv_pack<<<(16*NN)/256, 256>>>(points);

    dim3 ga(16, 16);
    attn_mma<<<ga, 256>>>();

    dim3 go(M_TOT/64, CC/64);
    gemm_o<<<go, 256>>>(Wo, bo);

    ln_kernel<<<M_TOT, 256>>>(feature, ln_g, ln_b, out);
}

// round 9
// speedup vs baseline: 3.6148x; 1.1559x over previous
#include <cuda_runtime.h>
#include <cuda_bf16.h>
#include <cstdint>

#define BB 2
#define NN 2048
#define CC 256
#define HH 8
#define HD 32
#define M_TOT (BB*NN)
#define QK_SCALE 0.17677669529663687f
#define LOG2E 1.4426950408889634f

typedef unsigned long long u64;

// ---------------- scratch (static device memory) -----------------------------
__device__ float g_q[(size_t)BB*HH*NN*HD];   // [bh][n][32] scaled by QK_SCALE
__device__ float g_k[(size_t)BB*HH*NN*HD];
__device__ float g_v[(size_t)BB*HH*NN*HD];
__device__ float g_att[(size_t)M_TOT*CC];
__device__ float g_o[(size_t)M_TOT*CC];
// attention packed operands
__device__ uint4 g_qt[(size_t)16*NN*11];   // [bh][n][88] = [qhi(36)|qlo(36)|0(16)] *LOG2E
__device__ uint4 g_ktp[(size_t)16*NN*11];  // [bh][n][88] = [khi(36)|khi(36)|0(16)]
__device__ uint4 g_vtp[(size_t)16*NN*5];   // [bh][n][40] = [v(32)|0(8)]
// projection-GEMM packed operands (3-term split, 768 bf16 = 96 uint4 per row)
__device__ uint4 g_fs[(size_t)M_TOT*96];   // feature rows: [hi|lo|hi]
__device__ uint4 g_os[(size_t)M_TOT*96];   // attention-out rows: [hi|lo|hi]
__device__ uint4 g_ws[(size_t)768*96];     // fused Wq|Wk|Wv cols: [hi|hi|lo]
__device__ uint4 g_wos[(size_t)256*96];    // Wo cols: [hi|hi|lo]

// ---------------- helpers -----------------------------------------------------
__device__ __forceinline__ uint32_t smem_u32(const void* p) {
    uint32_t a;
    asm("{ .reg .u64 t; cvta.to.shared.u64 t, %1; cvt.u32.u64 %0, t; }" : "=r"(a) : "l"(p));
    return a;
}
#define LDSM_X4(r, a) \
    asm volatile("ldmatrix.sync.aligned.m8n8.x4.shared.b16 {%0,%1,%2,%3}, [%4];" \
        : "=r"((r)[0]), "=r"((r)[1]), "=r"((r)[2]), "=r"((r)[3]) : "r"(a))
#define LDSM_X2(r, a) \
    asm volatile("ldmatrix.sync.aligned.m8n8.x2.shared.b16 {%0,%1}, [%2];" \
        : "=r"((r)[0]), "=r"((r)[1]) : "r"(a))
#define LDSM_X4T(r, a) \
    asm volatile("ldmatrix.sync.aligned.m8n8.x4.trans.shared.b16 {%0,%1,%2,%3}, [%4];" \
        : "=r"((r)[0]), "=r"((r)[1]), "=r"((r)[2]), "=r"((r)[3]) : "r"(a))
#define MMA16816(d, a, b0, b1) \
    asm volatile("mma.sync.aligned.m16n8k16.row.col.f32.bf16.bf16.f32 " \
        "{%0,%1,%2,%3}, {%4,%5,%6,%7}, {%8,%9}, {%0,%1,%2,%3};" \
        : "+f"((d)[0]), "+f"((d)[1]), "+f"((d)[2]), "+f"((d)[3]) \
        : "r"((a)[0]), "r"((a)[1]), "r"((a)[2]), "r"((a)[3]), "r"(b0), "r"(b1))
#define CP_ASYNC16(dst_u32, src) \
    asm volatile("cp.async.cg.shared.global [%0], [%1], 16;" :: "r"(dst_u32), "l"(src))
#define CP_COMMIT() asm volatile("cp.async.commit_group;" ::: "memory")
#define CP_WAIT(n)  asm volatile("cp.async.wait_group %0;" :: "n"(n) : "memory")

__device__ __forceinline__ void bf16_split(float v, unsigned short& hi, unsigned short& lo) {
    __nv_bfloat16 h = __float2bfloat16(v);
    __nv_bfloat16 l = __float2bfloat16(v - __bfloat162float(h));
    hi = *(unsigned short*)&h;
    lo = *(unsigned short*)&l;
}

// =============================================================================
// pack_split: fp32 [4096 x 256] rows -> bf16 rows [hi(256)|lo(256)|hi(256)]
// (96 uint4 per row; sections at uint4 offsets 0 / 32 / 64)
// =============================================================================
__global__ void __launch_bounds__(256)
pack_split(const float* __restrict__ ext, int use_att) {
    int t = blockIdx.x * 256 + threadIdx.x;
    int row = t >> 5, cg = t & 31;
    const float* src = (use_att ? (const float*)g_att : ext) + (size_t)row*CC + cg*8;
    float4 f0 = *(const float4*)src;
    float4 f1 = *(const float4*)(src + 4);
    float v[8] = {f0.x,f0.y,f0.z,f0.w,f1.x,f1.y,f1.z,f1.w};
    unsigned short hi[8], lo[8];
    #pragma unroll
    for (int u = 0; u < 8; u++) bf16_split(v[u], hi[u], lo[u]);
    uint4 wh, wl;
    wh.x = (uint32_t)hi[0] | ((uint32_t)hi[1] << 16);
    wh.y = (uint32_t)hi[2] | ((uint32_t)hi[3] << 16);
    wh.z = (uint32_t)hi[4] | ((uint32_t)hi[5] << 16);
    wh.w = (uint32_t)hi[6] | ((uint32_t)hi[7] << 16);
    wl.x = (uint32_t)lo[0] | ((uint32_t)lo[1] << 16);
    wl.y = (uint32_t)lo[2] | ((uint32_t)lo[3] << 16);
    wl.z = (uint32_t)lo[4] | ((uint32_t)lo[5] << 16);
    wl.w = (uint32_t)lo[6] | ((uint32_t)lo[7] << 16);
    uint4* dst = (use_att ? g_os : g_fs) + (size_t)row*96;
    dst[cg]      = wh;
    dst[32 + cg] = wl;
    dst[64 + cg] = wh;
}

// =============================================================================
// pack_wts: W columns -> bf16 rows [hi(256)|hi(256)|lo(256)].
// rows 0..767 = Wq|Wk|Wv cols -> g_ws; rows 768..1023 = Wo cols -> g_wos.
// =============================================================================
__global__ void __launch_bounds__(256)
pack_wts(const float* __restrict__ Wq, const float* __restrict__ Wk,
         const float* __restrict__ Wv, const float* __restrict__ Wo) {
    int t = blockIdx.x * 256 + threadIdx.x;
    int row = t >> 5, cg = t & 31;
    int z = row >> 8, cc = row & 255;
    const float* W = (z == 0) ? Wq : (z == 1) ? Wk : (z == 2) ? Wv : Wo;
    unsigned short hi[8], lo[8];
    #pragma unroll
    for (int u = 0; u < 8; u++)
        bf16_split(W[(size_t)(cg*8 + u)*CC + cc], hi[u], lo[u]);
    uint4 wh, wl;
    wh.x = (uint32_t)hi[0] | ((uint32_t)hi[1] << 16);
    wh.y = (uint32_t)hi[2] | ((uint32_t)hi[3] << 16);
    wh.z = (uint32_t)hi[4] | ((uint32_t)hi[5] << 16);
    wh.w = (uint32_t)hi[6] | ((uint32_t)hi[7] << 16);
    wl.x = (uint32_t)lo[0] | ((uint32_t)lo[1] << 16);
    wl.y = (uint32_t)lo[2] | ((uint32_t)lo[3] << 16);
    wl.z = (uint32_t)lo[4] | ((uint32_t)lo[5] << 16);
    wl.w = (uint32_t)lo[6] | ((uint32_t)lo[7] << 16);
    uint4* dst = (z < 3) ? (g_ws + (size_t)row*96) : (g_wos + (size_t)(row - 768)*96);
    dst[cg]      = wh;
    dst[32 + cg] = wh;
    dst[64 + cg] = wl;
}

// =============================================================================
// mma_mainloop: C[128 x 64] = A[128 x 768] * B[64 x 768]^T (both bf16 rows,
// 96 uint4 stride). 256 threads, 8 warps x 16 rows. k32 steps, double-buffered.
// smem row stride 40 bf16 (80B) -> conflict-free ldmatrix.
// =============================================================================
__device__ __forceinline__ void mma_mainloop(const uint4* __restrict__ Ap,
                                             const uint4* __restrict__ Bp,
                                             float oc[8][4]) {
    __shared__ __align__(16) unsigned short sA[2][128*40];  // 10240 B each
    __shared__ __align__(16) unsigned short sB[2][64*40];   // 5120 B each

    const int tid  = threadIdx.x;
    const int lane = tid & 31;
    const int wid  = tid >> 5;
    const int bx = blockIdx.x, by = blockIdx.y;

    #pragma unroll
    for (int i = 0; i < 8; i++)
        #pragma unroll
        for (int j = 0; j < 4; j++) oc[i][j] = 0.f;

    // prefetch iter 0
    {
        uint32_t ad = smem_u32(&sA[0][0]);
        uint32_t bd = smem_u32(&sB[0][0]);
        for (int i = tid; i < 512; i += 256) {
            int r = i >> 2, j = i & 3;
            CP_ASYNC16(ad + r*80 + j*16, Ap + (size_t)(bx*128 + r)*96 + j);
        }
        {
            int r = tid >> 2, j = tid & 3;
            CP_ASYNC16(bd + r*80 + j*16, Bp + (size_t)(by*64 + r)*96 + j);
        }
        CP_COMMIT();
    }

    for (int t = 0; t < 24; t++) {
        if (t < 23) {
            int nb = (t + 1) & 1;
            uint32_t ad = smem_u32(&sA[nb][0]);
            uint32_t bd = smem_u32(&sB[nb][0]);
            for (int i = tid; i < 512; i += 256) {
                int r = i >> 2, j = i & 3;
                CP_ASYNC16(ad + r*80 + j*16, Ap + (size_t)(bx*128 + r)*96 + (t+1)*4 + j);
            }
            {
                int r = tid >> 2, j = tid & 3;
                CP_ASYNC16(bd + r*80 + j*16, Bp + (size_t)(by*64 + r)*96 + (t+1)*4 + j);
            }
            CP_COMMIT();
            CP_WAIT(1);
        } else {
            CP_WAIT(0);
        }
        __syncthreads();

        const int buf = t & 1;
        uint32_t qa[2][4];
        uint32_t abase = smem_u32(&sA[buf][0]) + (wid*16 + (lane & 15))*80 + (lane >> 4)*16;
        LDSM_X4(qa[0], abase);
        LDSM_X4(qa[1], abase + 32);
        uint32_t bbase = smem_u32(&sB[buf][0]) + (lane & 7)*80 + ((lane >> 3) & 3)*16;
        #pragma unroll
        for (int nt = 0; nt < 8; nt++) {
            uint32_t kb[4];
            LDSM_X4(kb, bbase + nt*640);
            MMA16816(oc[nt], qa[0], kb[0], kb[1]);
            MMA16816(oc[nt], qa[1], kb[2], kb[3]);
        }
        __syncthreads();
    }
}

// =============================================================================
// gemm_qkv_mma: [feature split] x [Wq|Wk|Wv split] -> g_q/g_k/g_v (scattered)
// grid (32, 12)
// =============================================================================
__global__ void __launch_bounds__(256, 2)
gemm_qkv_mma(const float* __restrict__ bq, const float* __restrict__ bk,
             const float* __restrict__ bv) {
    float oc[8][4];
    mma_mainloop(g_fs, g_ws, oc);

    const int lane = threadIdx.x & 31;
    const int wid  = threadIdx.x >> 5;
    const int g  = lane >> 2;
    const int tq = lane & 3;
    const int r0 = blockIdx.x*128 + wid*16 + g;

    #pragma unroll
    for (int nt = 0; nt < 8; nt++) {
        int Cg = blockIdx.y*64 + nt*8 + 2*tq;
        int z = Cg >> 8, cc = Cg & 255;
        int h = cc >> 5, d = cc & 31;
        const float* bias = (z == 0) ? bq : (z == 1) ? bk : bv;
        float bb0 = bias[cc], bb1 = bias[cc + 1];
        float scale = (z == 0) ? QK_SCALE : 1.f;
        float* dbuf = (z == 0) ? g_q : (z == 1) ? g_k : g_v;
        #pragma unroll
        for (int half = 0; half < 2; half++) {
            int r = r0 + half*8;
            int b = r >> 11, n = r & (NN - 1);
            size_t idx = ((((size_t)b*HH + h)*NN + n))*HD + d;
            *(float2*)(dbuf + idx) = make_float2(
                (oc[nt][half*2 + 0] + bb0) * scale,
                (oc[nt][half*2 + 1] + bb1) * scale);
        }
    }
}

// =============================================================================
// gemm_o_mma: [att split] x [Wo split] -> g_o.  grid (32, 4)
// =============================================================================
__global__ void __launch_bounds__(256, 2)
gemm_o_mma(const float* __restrict__ bo) {
    float oc[8][4];
    mma_mainloop(g_os, g_wos, oc);

    const int lane = threadIdx.x & 31;
    const int wid  = threadIdx.x >> 5;
    const int g  = lane >> 2;
    const int tq = lane & 3;
    const int r0 = blockIdx.x*128 + wid*16 + g;

    #pragma unroll
    for (int nt = 0; nt < 8; nt++) {
        int Cg = blockIdx.y*64 + nt*8 + 2*tq;
        float bb0 = bo[Cg], bb1 = bo[Cg + 1];
        #pragma unroll
        for (int half = 0; half < 2; half++) {
            int r = r0 + half*8;
            *(float2*)(g_o + (size_t)r*CC + Cg) = make_float2(
                oc[nt][half*2 + 0] + bb0, oc[nt][half*2 + 1] + bb1);
        }
    }
}

// =============================================================================
// conv_pack: attention operand packs (aug dims from points) — round-6 passing
// =============================================================================
__global__ void __launch_bounds__(256)
conv_pack(const float* __restrict__ pts) {
    int t = blockIdx.x * 256 + threadIdx.x;
    if (t >= 16*NN) return;
    int bh = t >> 11, n = t & (NN-1);
    int b = bh >> 3;
    int m = b*NN + n;
    float px = pts[m*3+0], py = pts[m*3+1], pz = pts[m*3+2];
    float p2 = px*px + py*py + pz*pz;

    // Q: [hi|lo] of (q*LOG2E), aug {2p, 1}
    {
        const float* src = g_q + (size_t)t * HD;
        float qv[36];
        #pragma unroll
        for (int i = 0; i < 8; i++) {
            float4 f = *(const float4*)(src + 4*i);
            qv[4*i]   = f.x*LOG2E; qv[4*i+1] = f.y*LOG2E;
            qv[4*i+2] = f.z*LOG2E; qv[4*i+3] = f.w*LOG2E;
        }
        qv[32] = 2.f*px*LOG2E; qv[33] = 2.f*py*LOG2E;
        qv[34] = 2.f*pz*LOG2E; qv[35] = LOG2E;
        unsigned short hi[36], lo[36];
        #pragma unroll
        for (int i = 0; i < 36; i++) bf16_split(qv[i], hi[i], lo[i]);
        uint4* dst = g_qt + (size_t)t * 11;
        #pragma unroll
        for (int j = 0; j < 11; j++) {
            unsigned short e[8];
            #pragma unroll
            for (int u = 0; u < 8; u++) {
                int c = j*8 + u;
                e[u] = (c < 36) ? hi[c] : (c < 72) ? lo[c-36] : (unsigned short)0;
            }
            uint4 w;
            w.x = (uint32_t)e[0] | ((uint32_t)e[1] << 16);
            w.y = (uint32_t)e[2] | ((uint32_t)e[3] << 16);
            w.z = (uint32_t)e[4] | ((uint32_t)e[5] << 16);
            w.w = (uint32_t)e[6] | ((uint32_t)e[7] << 16);
            dst[j] = w;
        }
    }
    // K: [hi|hi], aug {p, -|p|^2}
    {
        const float* src = g_k + (size_t)t * HD;
        float kv[36];
        #pragma unroll
        for (int i = 0; i < 8; i++) {
            float4 f = *(const float4*)(src + 4*i);
            kv[4*i] = f.x; kv[4*i+1] = f.y; kv[4*i+2] = f.z; kv[4*i+3] = f.w;
        }
        kv[32] = px; kv[33] = py; kv[34] = pz; kv[35] = -p2;
        unsigned short hi[36];
        #pragma unroll
        for (int i = 0; i < 36; i++) {
            __nv_bfloat16 h = __float2bfloat16(kv[i]);
            hi[i] = *(unsigned short*)&h;
        }
        uint4* dst = g_ktp + (size_t)t * 11;
        #pragma unroll
        for (int j = 0; j < 11; j++) {
            unsigned short e[8];
            #pragma unroll
            for (int u = 0; u < 8; u++) {
                int c = j*8 + u;
                e[u] = (c < 36) ? hi[c] : (c < 72) ? hi[c-36] : (unsigned short)0;
            }
            uint4 w;
            w.x = (uint32_t)e[0] | ((uint32_t)e[1] << 16);
            w.y = (uint32_t)e[2] | ((uint32_t)e[3] << 16);
            w.z = (uint32_t)e[4] | ((uint32_t)e[5] << 16);
            w.w = (uint32_t)e[6] | ((uint32_t)e[7] << 16);
            dst[j] = w;
        }
    }
    // V
    {
        const float* src = g_v + (size_t)t * HD;
        uint4* dst = g_vtp + (size_t)t * 5;
        #pragma unroll
        for (int j = 0; j < 5; j++) {
            unsigned short e[8];
            #pragma unroll
            for (int u = 0; u < 8; u++) {
                int c = j*8 + u;
                if (c < 32) {
                    __nv_bfloat16 h = __float2bfloat16(src[c]);
                    e[u] = *(unsigned short*)&h;
                } else e[u] = 0;
            }
            uint4 w;
            w.x = (uint32_t)e[0] | ((uint32_t)e[1] << 16);
            w.y = (uint32_t)e[2] | ((uint32_t)e[3] << 16);
            w.z = (uint32_t)e[4] | ((uint32_t)e[5] << 16);
            w.w = (uint32_t)e[6] | ((uint32_t)e[7] << 16);
            dst[j] = w;
        }
    }
}

// =============================================================================
// attn_mma: flash attention, m16n8k16 bf16, 2-term split — round-6 passing
// =============================================================================
#define KROW 88
#define VROW 40

__global__ void __launch_bounds__(256, 2)
attn_mma() {
    __shared__ __align__(16) unsigned short sK[2][64*KROW];
    __shared__ __align__(16) unsigned short sV[2][64*VROW];

    const int tid  = threadIdx.x;
    const int lane = tid & 31;
    const int wid  = tid >> 5;
    const int bh = blockIdx.y;
    const int qt = blockIdx.x;
    const int b = bh >> 3, h = bh & 7;

    {
        const uint4* src = g_qt + ((size_t)bh*NN + qt*128) * 11;
        uint4* dst = (uint4*)&sK[0][0];
        for (int i = tid; i < 1408; i += 256) dst[i] = src[i];
    }
    __syncthreads();

    uint32_t qa[5][4];
    {
        uint32_t qbase = smem_u32(&sK[0][0]) + (wid*16 + (lane & 15))*176 + (lane >> 4)*16;
        #pragma unroll
        for (int c = 0; c < 5; c++) LDSM_X4(qa[c], qbase + c*32);
    }
    __syncthreads();

    float oc[4][4];
    #pragma unroll
    for (int i = 0; i < 4; i++)
        #pragma unroll
        for (int j = 0; j < 4; j++) oc[i][j] = 0.f;
    float ls0 = 0.f, ls1 = 0.f;

    const uint4* kg_src = g_ktp + (size_t)bh*NN*11;
    const uint4* vg_src = g_vtp + (size_t)bh*NN*5;

    {
        uint32_t kd = smem_u32(&sK[0][0]);
        uint32_t vd = smem_u32(&sV[0][0]);
        for (int i = tid; i < 704; i += 256) CP_ASYNC16(kd + i*16, kg_src + i);
        for (int i = tid; i < 320; i += 256) CP_ASYNC16(vd + i*16, vg_src + i);
        CP_COMMIT();
    }

    for (int t = 0; t < 32; t++) {
        if (t < 31) {
            int nb = (t + 1) & 1;
            uint32_t kd = smem_u32(&sK[nb][0]);
            uint32_t vd = smem_u32(&sV[nb][0]);
            const uint4* ks = kg_src + (size_t)(t+1)*64*11;
            const uint4* vs = vg_src + (size_t)(t+1)*64*5;
            for (int i = tid; i < 704; i += 256) CP_ASYNC16(kd + i*16, ks + i);
            for (int i = tid; i < 320; i += 256) CP_ASYNC16(vd + i*16, vs + i);
            CP_COMMIT();
            CP_WAIT(1);
        } else {
            CP_WAIT(0);
        }
        __syncthreads();

        const int buf = t & 1;
        uint32_t kbase = smem_u32(&sK[buf][0]);
        uint32_t vbase = smem_u32(&sV[buf][0]);

        float sc[8][4];
        #pragma unroll
        for (int kg = 0; kg < 8; kg++) {
            #pragma unroll
            for (int j = 0; j < 4; j++) sc[kg][j] = 0.f;
            uint32_t kb[10];
            uint32_t krow = kbase + (kg*8 + (lane & 7))*176;
            uint32_t ka = krow + ((lane >> 3) & 3)*16;
            LDSM_X4(&kb[0], ka);
            LDSM_X4(&kb[4], ka + 64);
            LDSM_X2(&kb[8], krow + 128 + ((lane >> 3) & 1)*16);
            #pragma unroll
            for (int c = 0; c < 5; c++)
                MMA16816(sc[kg], qa[c], kb[2*c], kb[2*c+1]);
        }

        uint32_t pa[4][4];
        #pragma unroll
        for (int pc = 0; pc < 4; pc++) {
            float e[8];
            #pragma unroll
            for (int half = 0; half < 2; half++) {
                const float* s = sc[2*pc + half];
                #pragma unroll
                for (int j = 0; j < 4; j++)
                    asm("ex2.approx.f32 %0, %1;" : "=f"(e[half*4 + j]) : "f"(s[j]));
            }
            ls0 += (e[0] + e[1]) + (e[4] + e[5]);
            ls1 += (e[2] + e[3]) + (e[6] + e[7]);
            asm("cvt.rn.bf16x2.f32 %0, %1, %2;" : "=r"(pa[pc][0]) : "f"(e[1]), "f"(e[0]));
            asm("cvt.rn.bf16x2.f32 %0, %1, %2;" : "=r"(pa[pc][1]) : "f"(e[3]), "f"(e[2]));
            asm("cvt.rn.bf16x2.f32 %0, %1, %2;" : "=r"(pa[pc][2]) : "f"(e[5]), "f"(e[4]));
            asm("cvt.rn.bf16x2.f32 %0, %1, %2;" : "=r"(pa[pc][3]) : "f"(e[7]), "f"(e[6]));
        }

        #pragma unroll
        for (int hp = 0; hp < 2; hp++) {
            #pragma unroll
            for (int pc = 0; pc < 4; pc++) {
                uint32_t vb[4];
                uint32_t va = vbase + (pc*16 + (lane & 15))*80 + hp*32 + (lane >> 4)*16;
                LDSM_X4T(vb, va);
                MMA16816(oc[2*hp],     pa[pc], vb[0], vb[1]);
                MMA16816(oc[2*hp + 1], pa[pc], vb[2], vb[3]);
            }
        }
        __syncthreads();
    }

    ls0 += __shfl_xor_sync(0xFFFFFFFFu, ls0, 1);
    ls0 += __shfl_xor_sync(0xFFFFFFFFu, ls0, 2);
    ls1 += __shfl_xor_sync(0xFFFFFFFFu, ls1, 1);
    ls1 += __shfl_xor_sync(0xFFFFFFFFu, ls1, 2);
    float inv0 = 1.f / ls0;
    float inv1 = 1.f / ls1;

    const int g  = lane >> 2;
    const int tq = lane & 3;
    const int row0 = qt*128 + wid*16 + g;
    float* base = g_att + ((size_t)(b*NN + row0))*CC + h*HD;
    #pragma unroll
    for (int n = 0; n < 4; n++) {
        *(float2*)(base + n*8 + 2*tq)                = make_float2(oc[n][0]*inv0, oc[n][1]*inv0);
        *(float2*)(base + (size_t)8*CC + n*8 + 2*tq) = make_float2(oc[n][2]*inv1, oc[n][3]*inv1);
    }
}

// =============================================================================
// Residual + LayerNorm
// =============================================================================
__global__ void __launch_bounds__(256)
ln_kernel(const float* __restrict__ feat,
          const float* __restrict__ ln_g, const float* __restrict__ ln_b,
          float* __restrict__ out) {
    const int m = blockIdx.x;
    const int c = threadIdx.x;
    float f = feat[(size_t)m*CC + c] + g_o[(size_t)m*CC + c];

    __shared__ float red[256];
    red[c] = f;
    __syncthreads();
    #pragma unroll
    for (int s = 128; s > 0; s >>= 1) {
        if (c < s) red[c] += red[c + s];
        __syncthreads();
    }
    float mu = red[0] * (1.f/256.f);
    __syncthreads();
    float d = f - mu;
    red[c] = d * d;
    __syncthreads();
    #pragma unroll
    for (int s = 128; s > 0; s >>= 1) {
        if (c < s) red[c] += red[c + s];
        __syncthreads();
    }
    float var = red[0] * (1.f/256.f);
    out[(size_t)m*CC + c] = d * rsqrtf(var + 1e-5f) * ln_g[c] + ln_b[c];
}

// =============================================================================
extern "C" void kernel_launch(void* const* d_in, const int* in_sizes, int n_in,
                              void* d_out, int out_size) {
    const float* feature = (const float*)d_in[0];
    const float* points  = (const float*)d_in[1];
    const float* Wq = (const float*)d_in[2];
    const float* bq = (const float*)d_in[3];
    const float* Wk = (const float*)d_in[4];
    const float* bk = (const float*)d_in[5];
    const float* Wv = (const float*)d_in[6];
    const float* bv = (const float*)d_in[7];
    const float* Wo = (const float*)d_in[8];
    const float* bo = (const float*)d_in[9];
    const float* ln_g = (const float*)d_in[10];
    const float* ln_b = (const float*)d_in[11];
    float* out = (float*)d_out;

    pack_split<<<512, 256>>>(feature, 0);
    pack_wts<<<128, 256>>>(Wq, Wk, Wv, Wo);

    dim3 gq(32, 12);
    gemm_qkv_mma<<<gq, 256>>>(bq, bk, bv);

    conv_pack<<<128, 256>>>(points);

    dim3 ga(16, 16);
    attn_mma<<<ga, 256>>>();

    pack_split<<<512, 256>>>(nullptr, 1);

    dim3 go(32, 4);
    gemm_o_mma<<<go, 256>>>(bo);

    ln_kernel<<<M_TOT, 256>>>(feature, ln_g, ln_b, out);
}